// round 1
// baseline (speedup 1.0000x reference)
#include <cuda_runtime.h>
#include <cstring>

// Shapes
#define BB 32
#define TT 64
#define NN 300
#define DD 128
#define ND (NN*DD)          // 38400
#define BT (BB*TT)          // 2048

// Scratch (static __device__ — no allocation allowed)
__device__ float g_Q[BB*TT*NN];     // [b,t,n]
__device__ float g_K[BB*TT*DD];     // [b,t,d]
__device__ float g_M[BB*TT*DD];     // [b,q,d]
__device__ float g_S[BB*TT*TT];     // scores [b,q,k]
__device__ float g_A[BB*TT*TT];     // att    [b,t,a]

// ---------------------------------------------------------------------------
// Kernel 1: Q[bt,n] = dot(src[bt,n,:], wt1);  K[bt,d] = sum_n wt3[n]*src[bt,n,d]
// grid = 2048 blocks (one per (b,t)), 256 threads.
// ---------------------------------------------------------------------------
__global__ void qk_kernel(const float* __restrict__ src,
                          const float* __restrict__ wt1,
                          const float* __restrict__ wt3) {
    const int bt  = blockIdx.x;
    const int tid = threadIdx.x;
    const float* base = src + (size_t)bt * ND;

    __shared__ float sw3[NN];
    __shared__ float sk[256];
    for (int i = tid; i < NN; i += 256) sw3[i] = wt3[i];
    __syncthreads();

    // ---- Q phase: warp per row group ----
    const int warp = tid >> 5, lane = tid & 31;
    const float4 w1v = reinterpret_cast<const float4*>(wt1)[lane];  // wt1[4*lane..]
    for (int n = warp; n < NN; n += 8) {
        const float4 v = reinterpret_cast<const float4*>(base + n * DD)[lane];
        float p = v.x * w1v.x + v.y * w1v.y + v.z * w1v.z + v.w * w1v.w;
        #pragma unroll
        for (int off = 16; off > 0; off >>= 1)
            p += __shfl_xor_sync(0xffffffffu, p, off);
        if (lane == 0) g_Q[bt * NN + n] = p;
    }

    // ---- K phase: 2 halves of n per d ----
    const int half = tid >> 7;
    const int d    = tid & 127;
    float acc = 0.f;
    const int n0 = half * 150;
    #pragma unroll 4
    for (int n = n0; n < n0 + 150; ++n)
        acc += sw3[n] * base[n * DD + d];
    sk[tid] = acc;
    __syncthreads();
    if (tid < 128) g_K[bt * DD + tid] = sk[tid] + sk[tid + 128];
}

// ---------------------------------------------------------------------------
// Kernel 2: M[b,q,d] = sum_n Q[b,q,n] * wt2[n,d]
// grid = (32 b, 8 q-tiles of 8), 256 threads (8 warps, warp = q within tile)
// ---------------------------------------------------------------------------
__global__ void m_kernel(const float* __restrict__ wt2) {
    const int b = blockIdx.x, qt = blockIdx.y;
    const int tid = threadIdx.x;
    __shared__ float sQ[8 * NN];
    for (int i = tid; i < 8 * NN; i += 256)
        sQ[i] = g_Q[(b * TT + qt * 8) * NN + i];
    __syncthreads();

    const int warp = tid >> 5, lane = tid & 31;
    const float* qr = sQ + warp * NN;
    float acc[4] = {0.f, 0.f, 0.f, 0.f};
    #pragma unroll 4
    for (int n = 0; n < NN; ++n) {
        const float qv = qr[n];
        const float* w2 = wt2 + n * DD;
        #pragma unroll
        for (int j = 0; j < 4; ++j)
            acc[j] += qv * w2[lane + 32 * j];
    }
    const int q = qt * 8 + warp;
    #pragma unroll
    for (int j = 0; j < 4; ++j)
        g_M[(b * TT + q) * DD + lane + 32 * j] = acc[j];
}

// ---------------------------------------------------------------------------
// Kernel 3: scores[b,q,k] = sum_d M[b,q,d] * K[b,k,d]
// grid = (32 b, 4 q-tiles of 16), 256 threads
// ---------------------------------------------------------------------------
__global__ void scores_kernel() {
    const int b = blockIdx.x, qt = blockIdx.y;
    const int tid = threadIdx.x;
    __shared__ float sM[16 * DD];
    __shared__ float sK[TT * 129];   // pad to kill bank conflicts

    for (int i = tid; i < 16 * DD; i += 256)
        sM[i] = g_M[(b * TT + qt * 16) * DD + i];
    for (int i = tid; i < TT * DD; i += 256) {
        const int k = i >> 7, d = i & 127;
        sK[k * 129 + d] = g_K[(b * TT + k) * DD + d];
    }
    __syncthreads();

    #pragma unroll
    for (int pi = 0; pi < 4; ++pi) {
        const int p = tid + 256 * pi;       // 1024 (q,k) pairs
        const int q = p >> 6, k = p & 63;
        float acc = 0.f;
        #pragma unroll 8
        for (int d = 0; d < DD; ++d)
            acc += sM[q * DD + d] * sK[k * 129 + d];
        g_S[(b * TT + qt * 16 + q) * TT + k] = acc;
    }
}

// ---------------------------------------------------------------------------
// Kernel 4: att = softmax over BATCH axis.  lane = b (B==32 == warp size).
// grid = 512 blocks * 256 threads; warp handles one (q,k) pair.
// ---------------------------------------------------------------------------
__global__ void softmax_kernel() {
    const int warp = threadIdx.x >> 5, lane = threadIdx.x & 31;
    const int p = blockIdx.x * 8 + warp;            // p in [0, 4096)
    const float x = g_S[lane * (TT * TT) + p];
    float m = x;
    #pragma unroll
    for (int off = 16; off > 0; off >>= 1)
        m = fmaxf(m, __shfl_xor_sync(0xffffffffu, m, off));
    const float e = __expf(x - m);
    float s = e;
    #pragma unroll
    for (int off = 16; off > 0; off >>= 1)
        s += __shfl_xor_sync(0xffffffffu, s, off);
    g_A[lane * (TT * TT) + p] = e / s;
}

// ---------------------------------------------------------------------------
// Kernel 5: out[b,a,c] = sum_t (att[b,t,a] + I) * src[b,t,c]
// A' = att^T + I folded; packed f32x2 FFMA; thread = 2 adjacent columns.
// grid = (75 col-blocks, 32 b), 256 threads. A' pre-duplicated in smem so
// one broadcast LDS.128 feeds two fma.rn.f32x2.
// ---------------------------------------------------------------------------
__global__ void __launch_bounds__(256, 1)
mix_kernel(const float* __restrict__ src, float* __restrict__ out) {
    const int b   = blockIdx.y;
    const int tid = threadIdx.x;
    __shared__ __align__(16) unsigned long long sAp[TT * TT];  // [t][a], dup-packed

    const float* Ab = g_A + b * (TT * TT);
    for (int i = tid; i < TT * TT; i += 256) {
        const int t = i >> 6, a = i & 63;
        float v = Ab[i] + (t == a ? 1.0f : 0.0f);
        float2 f2 = make_float2(v, v);
        unsigned long long pv;
        memcpy(&pv, &f2, 8);
        sAp[i] = pv;
    }
    __syncthreads();

    const size_t colbase = (size_t)blockIdx.x * 512 + (size_t)tid * 2;
    const float* sb = src + (size_t)b * TT * ND + colbase;
    float* ob       = out + (size_t)b * TT * ND + colbase;

    // Load column-pair for all 64 time steps into registers (packed f32x2)
    unsigned long long x[TT];
    #pragma unroll
    for (int t = 0; t < TT; ++t)
        x[t] = *reinterpret_cast<const unsigned long long*>(sb + (size_t)t * ND);

    const ulonglong2* sAp2 = reinterpret_cast<const ulonglong2*>(sAp);
    for (int ap = 0; ap < 32; ++ap) {           // output rows a0 = 2*ap, 2*ap+1
        unsigned long long acc0 = 0ull, acc1 = 0ull;  // bits of (0.f, 0.f)
        #pragma unroll
        for (int t = 0; t < TT; ++t) {
            const ulonglong2 pa = sAp2[(t << 5) + ap];  // (A[t][a0]x2, A[t][a0+1]x2)
            asm("fma.rn.f32x2 %0, %1, %2, %0;" : "+l"(acc0) : "l"(x[t]), "l"(pa.x));
            asm("fma.rn.f32x2 %0, %1, %2, %0;" : "+l"(acc1) : "l"(x[t]), "l"(pa.y));
        }
        const int a0 = ap * 2;
        *reinterpret_cast<unsigned long long*>(ob + (size_t)a0       * ND) = acc0;
        *reinterpret_cast<unsigned long long*>(ob + (size_t)(a0 + 1) * ND) = acc1;
    }
}

// ---------------------------------------------------------------------------
extern "C" void kernel_launch(void* const* d_in, const int* in_sizes, int n_in,
                              void* d_out, int out_size) {
    const float *src = nullptr, *wt1 = nullptr, *wt2 = nullptr, *wt3 = nullptr;
    for (int i = 0; i < n_in; ++i) {
        const int s = in_sizes[i];
        if      (s == BB * TT * NN * DD) src = (const float*)d_in[i];
        else if (s == DD)                wt1 = (const float*)d_in[i];
        else if (s == NN * DD)           wt2 = (const float*)d_in[i];
        else if (s == NN)                wt3 = (const float*)d_in[i];
    }
    float* out = (float*)d_out;

    qk_kernel<<<BT, 256>>>(src, wt1, wt3);
    m_kernel<<<dim3(BB, 8), 256>>>(wt2);
    scores_kernel<<<dim3(BB, 4), 256>>>();
    softmax_kernel<<<512, 256>>>();
    mix_kernel<<<dim3(ND / 512, BB), 256>>>(src, out);
}

// round 2
// speedup vs baseline: 1.0778x; 1.0778x over previous
#include <cuda_runtime.h>
#include <cstring>
#include <cstdint>

// Shapes
#define BB 32
#define TT 64
#define NN 300
#define DD 128
#define ND (NN*DD)          // 38400
#define BT (BB*TT)          // 2048

// Scratch (static __device__ — no allocation allowed)
__device__ float g_Q[BB*TT*NN];     // [b,t,n]
__device__ float g_K[BB*TT*DD];     // [b,t,d]
__device__ float g_M[BB*TT*DD];     // [b,q,d]
__device__ float g_S[BB*TT*TT];     // scores [b,q,k]
__device__ float g_A[BB*TT*TT];     // att    [b,t,a]

// ---------------------------------------------------------------------------
// Kernel 1: Q[bt,n] = dot(src[bt,n,:], wt1);  K[bt,d] = sum_n wt3[n]*src[bt,n,d]
// ---------------------------------------------------------------------------
__global__ void qk_kernel(const float* __restrict__ src,
                          const float* __restrict__ wt1,
                          const float* __restrict__ wt3) {
    const int bt  = blockIdx.x;
    const int tid = threadIdx.x;
    const float* base = src + (size_t)bt * ND;

    __shared__ float sw3[NN];
    __shared__ float sk[256];
    for (int i = tid; i < NN; i += 256) sw3[i] = wt3[i];
    __syncthreads();

    const int warp = tid >> 5, lane = tid & 31;
    const float4 w1v = reinterpret_cast<const float4*>(wt1)[lane];
    for (int n = warp; n < NN; n += 8) {
        const float4 v = reinterpret_cast<const float4*>(base + n * DD)[lane];
        float p = v.x * w1v.x + v.y * w1v.y + v.z * w1v.z + v.w * w1v.w;
        #pragma unroll
        for (int off = 16; off > 0; off >>= 1)
            p += __shfl_xor_sync(0xffffffffu, p, off);
        if (lane == 0) g_Q[bt * NN + n] = p;
    }

    const int half = tid >> 7;
    const int d    = tid & 127;
    float acc = 0.f;
    const int n0 = half * 150;
    #pragma unroll 4
    for (int n = n0; n < n0 + 150; ++n)
        acc += sw3[n] * base[n * DD + d];
    sk[tid] = acc;
    __syncthreads();
    if (tid < 128) g_K[bt * DD + tid] = sk[tid] + sk[tid + 128];
}

// ---------------------------------------------------------------------------
// Kernel 2: M[b,q,d] = sum_n Q[b,q,n] * wt2[n,d]
// ---------------------------------------------------------------------------
__global__ void m_kernel(const float* __restrict__ wt2) {
    const int b = blockIdx.x, qt = blockIdx.y;
    const int tid = threadIdx.x;
    __shared__ float sQ[8 * NN];
    for (int i = tid; i < 8 * NN; i += 256)
        sQ[i] = g_Q[(b * TT + qt * 8) * NN + i];
    __syncthreads();

    const int warp = tid >> 5, lane = tid & 31;
    const float* qr = sQ + warp * NN;
    float acc[4] = {0.f, 0.f, 0.f, 0.f};
    #pragma unroll 4
    for (int n = 0; n < NN; ++n) {
        const float qv = qr[n];
        const float* w2 = wt2 + n * DD;
        #pragma unroll
        for (int j = 0; j < 4; ++j)
            acc[j] += qv * w2[lane + 32 * j];
    }
    const int q = qt * 8 + warp;
    #pragma unroll
    for (int j = 0; j < 4; ++j)
        g_M[(b * TT + q) * DD + lane + 32 * j] = acc[j];
}

// ---------------------------------------------------------------------------
// Kernel 3: scores[b,q,k] = sum_d M[b,q,d] * K[b,k,d]
// ---------------------------------------------------------------------------
__global__ void scores_kernel() {
    const int b = blockIdx.x, qt = blockIdx.y;
    const int tid = threadIdx.x;
    __shared__ float sM[16 * DD];
    __shared__ float sK[TT * 129];

    for (int i = tid; i < 16 * DD; i += 256)
        sM[i] = g_M[(b * TT + qt * 16) * DD + i];
    for (int i = tid; i < TT * DD; i += 256) {
        const int k = i >> 7, d = i & 127;
        sK[k * 129 + d] = g_K[(b * TT + k) * DD + d];
    }
    __syncthreads();

    #pragma unroll
    for (int pi = 0; pi < 4; ++pi) {
        const int p = tid + 256 * pi;
        const int q = p >> 6, k = p & 63;
        float acc = 0.f;
        #pragma unroll 8
        for (int d = 0; d < DD; ++d)
            acc += sM[q * DD + d] * sK[k * 129 + d];
        g_S[(b * TT + qt * 16 + q) * TT + k] = acc;
    }
}

// ---------------------------------------------------------------------------
// Kernel 4: att = softmax over BATCH axis. lane = b.
// ---------------------------------------------------------------------------
__global__ void softmax_kernel() {
    const int warp = threadIdx.x >> 5, lane = threadIdx.x & 31;
    const int p = blockIdx.x * 8 + warp;
    const float x = g_S[lane * (TT * TT) + p];
    float m = x;
    #pragma unroll
    for (int off = 16; off > 0; off >>= 1)
        m = fmaxf(m, __shfl_xor_sync(0xffffffffu, m, off));
    const float e = __expf(x - m);
    float s = e;
    #pragma unroll
    for (int off = 16; off > 0; off >>= 1)
        s += __shfl_xor_sync(0xffffffffu, s, off);
    g_A[lane * (TT * TT) + p] = e / s;
}

// ---------------------------------------------------------------------------
// Kernel 5 (TENSOR): out[b,a,c] = sum_t A'[a,t]*src[b,t,c],  A' = att^T + I.
// 3xTF32 mma.sync.m16n8k8: D += Ah*Bh + Al*Bh + Ah*Bl  (error ~2^-22).
// CTA = 128 threads, handles (b, 128-col tile). Warp w = full M=64, 32 cols.
// ---------------------------------------------------------------------------
#define SS_STRIDE 136   // 128 + 8  -> B-frag LDS conflict-free (8r+c perm)
#define SA_STRIDE 68    // 64 + 4   -> A-frag LDS conflict-free (4a+t perm)
#define MIX_SMEM_BYTES ((TT*SS_STRIDE)*4 + (TT*SA_STRIDE)*4*2)   // 69632

__device__ __forceinline__ void split_tf32(float v, uint32_t& hi, uint32_t& lo) {
    asm("cvt.rna.tf32.f32 %0, %1;" : "=r"(hi) : "f"(v));
    float r = v - __uint_as_float(hi);
    asm("cvt.rna.tf32.f32 %0, %1;" : "=r"(lo) : "f"(r));
}

__device__ __forceinline__ void mma_tf32(float c[4],
                                         uint32_t a0, uint32_t a1, uint32_t a2, uint32_t a3,
                                         uint32_t b0, uint32_t b1) {
    asm volatile(
        "mma.sync.aligned.m16n8k8.row.col.f32.tf32.tf32.f32 "
        "{%0,%1,%2,%3}, {%4,%5,%6,%7}, {%8,%9}, {%0,%1,%2,%3};"
        : "+f"(c[0]), "+f"(c[1]), "+f"(c[2]), "+f"(c[3])
        : "r"(a0), "r"(a1), "r"(a2), "r"(a3), "r"(b0), "r"(b1));
}

__global__ void __launch_bounds__(128)
mix_kernel(const float* __restrict__ src, float* __restrict__ out) {
    extern __shared__ float smem[];
    float*    sS  = smem;                            // [64][SS_STRIDE] src tile
    uint32_t* sAh = (uint32_t*)(smem + TT * SS_STRIDE);       // [64][SA_STRIDE]
    uint32_t* sAl = sAh + TT * SA_STRIDE;

    const int b   = blockIdx.y;
    const int tid = threadIdx.x;
    const int warp = tid >> 5, lane = tid & 31;
    const int colbase = blockIdx.x * 128;

    // --- A' prep: A'[a][t] = att[b][t][a] + (t==a), split into tf32 hi/lo ---
    const float* Ab = g_A + b * (TT * TT);
    for (int i = tid; i < TT * TT; i += 128) {
        const int t = i >> 6, a = i & 63;
        float v = Ab[i] + (t == a ? 1.0f : 0.0f);
        uint32_t hi, lo;
        split_tf32(v, hi, lo);
        sAh[a * SA_STRIDE + t] = hi;
        sAl[a * SA_STRIDE + t] = lo;
    }

    // --- src tile: sS[t][c] = src[b][t][colbase+c], 64x128 via float4 ---
    const float* sb = src + (size_t)b * TT * ND + colbase;
    for (int i = tid; i < TT * 32; i += 128) {       // 2048 float4
        const int t = i >> 5, c4 = i & 31;
        const float4 v = *reinterpret_cast<const float4*>(sb + (size_t)t * ND + c4 * 4);
        *reinterpret_cast<float4*>(sS + t * SS_STRIDE + c4 * 4) = v;
    }
    __syncthreads();

    const int g  = lane >> 2;       // 0..7
    const int tg = lane & 3;        // 0..3
    const int n0w = warp * 32;      // this warp's 32-col slice

    float acc[4][4][4];             // [mt][nt][frag]
    #pragma unroll
    for (int mt = 0; mt < 4; ++mt)
        #pragma unroll
        for (int nt = 0; nt < 4; ++nt)
            #pragma unroll
            for (int f = 0; f < 4; ++f) acc[mt][nt][f] = 0.f;

    #pragma unroll
    for (int ks = 0; ks < 8; ++ks) {
        const int kk = ks * 8;
        uint32_t ah[4][4], al[4][4];
        #pragma unroll
        for (int mt = 0; mt < 4; ++mt) {
            const int r0 = (mt * 16 + g) * SA_STRIDE + kk + tg;
            const int r1 = r0 + 8 * SA_STRIDE;
            ah[mt][0] = sAh[r0];     ah[mt][1] = sAh[r1];
            ah[mt][2] = sAh[r0 + 4]; ah[mt][3] = sAh[r1 + 4];
            al[mt][0] = sAl[r0];     al[mt][1] = sAl[r1];
            al[mt][2] = sAl[r0 + 4]; al[mt][3] = sAl[r1 + 4];
        }
        #pragma unroll
        for (int nt = 0; nt < 4; ++nt) {
            const int nbase = n0w + nt * 8 + g;
            const float b0f = sS[(kk + tg)     * SS_STRIDE + nbase];
            const float b1f = sS[(kk + tg + 4) * SS_STRIDE + nbase];
            uint32_t bh0, bl0, bh1, bl1;
            split_tf32(b0f, bh0, bl0);
            split_tf32(b1f, bh1, bl1);
            #pragma unroll
            for (int mt = 0; mt < 4; ++mt) {
                mma_tf32(acc[mt][nt], ah[mt][0], ah[mt][1], ah[mt][2], ah[mt][3], bh0, bh1);
                mma_tf32(acc[mt][nt], al[mt][0], al[mt][1], al[mt][2], al[mt][3], bh0, bh1);
                mma_tf32(acc[mt][nt], ah[mt][0], ah[mt][1], ah[mt][2], ah[mt][3], bl0, bl1);
            }
        }
    }

    // --- epilogue: store (residual already folded via I in A') ---
    float* ob = out + (size_t)b * TT * ND + colbase;
    #pragma unroll
    for (int mt = 0; mt < 4; ++mt) {
        const int a0 = mt * 16 + g;
        #pragma unroll
        for (int nt = 0; nt < 4; ++nt) {
            const int c = n0w + nt * 8 + 2 * tg;
            float2 v0 = make_float2(acc[mt][nt][0], acc[mt][nt][1]);
            float2 v1 = make_float2(acc[mt][nt][2], acc[mt][nt][3]);
            *reinterpret_cast<float2*>(ob + (size_t)a0       * ND + c) = v0;
            *reinterpret_cast<float2*>(ob + (size_t)(a0 + 8) * ND + c) = v1;
        }
    }
}

// ---------------------------------------------------------------------------
extern "C" void kernel_launch(void* const* d_in, const int* in_sizes, int n_in,
                              void* d_out, int out_size) {
    const float *src = nullptr, *wt1 = nullptr, *wt2 = nullptr, *wt3 = nullptr;
    for (int i = 0; i < n_in; ++i) {
        const int s = in_sizes[i];
        if      (s == BB * TT * NN * DD) src = (const float*)d_in[i];
        else if (s == DD)                wt1 = (const float*)d_in[i];
        else if (s == NN * DD)           wt2 = (const float*)d_in[i];
        else if (s == NN)                wt3 = (const float*)d_in[i];
    }
    float* out = (float*)d_out;

    static bool attr_done = false;
    if (!attr_done) {
        cudaFuncSetAttribute(mix_kernel,
                             cudaFuncAttributeMaxDynamicSharedMemorySize,
                             MIX_SMEM_BYTES);
        attr_done = true;
    }

    qk_kernel<<<BT, 256>>>(src, wt1, wt3);
    m_kernel<<<dim3(BB, 8), 256>>>(wt2);
    scores_kernel<<<dim3(BB, 4), 256>>>();
    softmax_kernel<<<512, 256>>>();
    mix_kernel<<<dim3(ND / 128, BB), 256 / 2, MIX_SMEM_BYTES>>>(src, out);
}

// round 3
// speedup vs baseline: 1.9221x; 1.7833x over previous
#include <cuda_runtime.h>
#include <cuda_bf16.h>
#include <cstring>
#include <cstdint>

// Shapes
#define BB 32
#define TT 64
#define NN 300
#define DD 128
#define ND (NN*DD)          // 38400
#define BT (BB*TT)          // 2048

// Scratch (static __device__ — no allocation allowed)
__device__ float g_Q[BB*TT*NN];     // [b,t,n]
__device__ float g_K[BB*TT*DD];     // [b,t,d]
__device__ float g_M[BB*TT*DD];     // [b,q,d]
__device__ float g_S[BB*TT*TT];     // scores [b,q,k]
__device__ float g_A[BB*TT*TT];     // att    [b,t,a]

// ---------------------------------------------------------------------------
// Kernel 1 (FUSED, single pass over src):
//   Q[bt,n] = dot(src[bt,n,:], wt1)
//   K[bt,d] = sum_n wt3[n] * src[bt,n,d]
// One block per (b,t); each float4 of src is loaded exactly once.
// ---------------------------------------------------------------------------
__global__ void qk_kernel(const float* __restrict__ src,
                          const float* __restrict__ wt1,
                          const float* __restrict__ wt3) {
    const int bt  = blockIdx.x;
    const int tid = threadIdx.x;
    const float* base = src + (size_t)bt * ND;

    __shared__ float  sw3[NN];
    __shared__ float4 sKred[8][32];
    for (int i = tid; i < NN; i += 256) sw3[i] = wt3[i];
    __syncthreads();

    const int warp = tid >> 5, lane = tid & 31;
    const float4 w1v = reinterpret_cast<const float4*>(wt1)[lane];
    float4 kacc = make_float4(0.f, 0.f, 0.f, 0.f);

    #pragma unroll 2
    for (int n = warp; n < NN; n += 8) {
        const float4 v = reinterpret_cast<const float4*>(base + n * DD)[lane];
        const float w3n = sw3[n];
        kacc.x += w3n * v.x; kacc.y += w3n * v.y;
        kacc.z += w3n * v.z; kacc.w += w3n * v.w;
        float p = v.x * w1v.x + v.y * w1v.y + v.z * w1v.z + v.w * w1v.w;
        #pragma unroll
        for (int off = 16; off > 0; off >>= 1)
            p += __shfl_xor_sync(0xffffffffu, p, off);
        if (lane == 0) g_Q[bt * NN + n] = p;
    }

    sKred[warp][lane] = kacc;
    __syncthreads();
    if (tid < 128) {
        const int l = tid >> 2, comp = tid & 3;
        float s = 0.f;
        #pragma unroll
        for (int w = 0; w < 8; ++w)
            s += reinterpret_cast<const float*>(&sKred[w][l])[comp];
        g_K[bt * DD + tid] = s;
    }
}

// ---------------------------------------------------------------------------
// Kernel 2: M[b,q,d] = sum_n Q[b,q,n] * wt2[n,d]
// ---------------------------------------------------------------------------
__global__ void m_kernel(const float* __restrict__ wt2) {
    const int b = blockIdx.x, qt = blockIdx.y;
    const int tid = threadIdx.x;
    __shared__ float sQ[8 * NN];
    for (int i = tid; i < 8 * NN; i += 256)
        sQ[i] = g_Q[(b * TT + qt * 8) * NN + i];
    __syncthreads();

    const int warp = tid >> 5, lane = tid & 31;
    const float* qr = sQ + warp * NN;
    float acc[4] = {0.f, 0.f, 0.f, 0.f};
    #pragma unroll 4
    for (int n = 0; n < NN; ++n) {
        const float qv = qr[n];
        const float* w2 = wt2 + n * DD;
        #pragma unroll
        for (int j = 0; j < 4; ++j)
            acc[j] += qv * w2[lane + 32 * j];
    }
    const int q = qt * 8 + warp;
    #pragma unroll
    for (int j = 0; j < 4; ++j)
        g_M[(b * TT + q) * DD + lane + 32 * j] = acc[j];
}

// ---------------------------------------------------------------------------
// Kernel 3: scores[b,q,k] = sum_d M[b,q,d] * K[b,k,d]
// ---------------------------------------------------------------------------
__global__ void scores_kernel() {
    const int b = blockIdx.x, qt = blockIdx.y;
    const int tid = threadIdx.x;
    __shared__ float sM[16 * DD];
    __shared__ float sK[TT * 129];

    for (int i = tid; i < 16 * DD; i += 256)
        sM[i] = g_M[(b * TT + qt * 16) * DD + i];
    for (int i = tid; i < TT * DD; i += 256) {
        const int k = i >> 7, d = i & 127;
        sK[k * 129 + d] = g_K[(b * TT + k) * DD + d];
    }
    __syncthreads();

    #pragma unroll
    for (int pi = 0; pi < 4; ++pi) {
        const int p = tid + 256 * pi;
        const int q = p >> 6, k = p & 63;
        float acc = 0.f;
        #pragma unroll 8
        for (int d = 0; d < DD; ++d)
            acc += sM[q * DD + d] * sK[k * 129 + d];
        g_S[(b * TT + qt * 16 + q) * TT + k] = acc;
    }
}

// ---------------------------------------------------------------------------
// Kernel 4: att = softmax over BATCH axis. lane = b.
// ---------------------------------------------------------------------------
__global__ void softmax_kernel() {
    const int warp = threadIdx.x >> 5, lane = threadIdx.x & 31;
    const int p = blockIdx.x * 8 + warp;
    const float x = g_S[lane * (TT * TT) + p];
    float m = x;
    #pragma unroll
    for (int off = 16; off > 0; off >>= 1)
        m = fmaxf(m, __shfl_xor_sync(0xffffffffu, m, off));
    const float e = __expf(x - m);
    float s = e;
    #pragma unroll
    for (int off = 16; off > 0; off >>= 1)
        s += __shfl_xor_sync(0xffffffffu, s, off);
    g_A[lane * (TT * TT) + p] = e / s;
}

// ---------------------------------------------------------------------------
// Kernel 5 (TENSOR, bf16 split): mixed[a,c] = sum_t att^T[a,t]*src[t,c]
// D = Ah*Sh + Al*Sh + Ah*Sl   (2x bf16 split, error ~2^-16)
// Residual +src added in FP32 in the epilogue from the smem tile.
// CTA = 128 threads = 4 warps, handles (b, 128-col tile).
// ---------------------------------------------------------------------------
#define SS_STRIDE 132   // floats; addr mod 32 = 4t + c  -> conflict-free
#define SA_STRIDE 36    // uint32; addr mod 32 = 4a + tp -> conflict-free
#define MIX_SMEM_BYTES (TT*SS_STRIDE*4 + 2*TT*SA_STRIDE*4)   // 52224

__device__ __forceinline__ float bf16_round(float v) {
    return __bfloat162float(__float2bfloat16_rn(v));
}
// pack two floats as bf16x2; 'lo' goes to bits [15:0] (lower k index)
__device__ __forceinline__ uint32_t pack_bf16x2(float lo, float hi) {
    uint32_t r;
    asm("cvt.rn.bf16x2.f32 %0, %1, %2;" : "=r"(r) : "f"(hi), "f"(lo));
    return r;
}

__device__ __forceinline__ void mma_bf16(float c[4], const uint32_t a[4],
                                         uint32_t b0, uint32_t b1) {
    asm volatile(
        "mma.sync.aligned.m16n8k16.row.col.f32.bf16.bf16.f32 "
        "{%0,%1,%2,%3}, {%4,%5,%6,%7}, {%8,%9}, {%0,%1,%2,%3};"
        : "+f"(c[0]), "+f"(c[1]), "+f"(c[2]), "+f"(c[3])
        : "r"(a[0]), "r"(a[1]), "r"(a[2]), "r"(a[3]), "r"(b0), "r"(b1));
}

__global__ void __launch_bounds__(128)
mix_kernel(const float* __restrict__ src, float* __restrict__ out) {
    extern __shared__ float smem[];
    float*    sS  = smem;                               // [64][SS_STRIDE] fp32
    uint32_t* sAh = (uint32_t*)(smem + TT * SS_STRIDE); // [64][SA_STRIDE] bf16x2
    uint32_t* sAl = sAh + TT * SA_STRIDE;

    const int b    = blockIdx.y;
    const int tid  = threadIdx.x;
    const int warp = tid >> 5, lane = tid & 31;
    const int colbase = blockIdx.x * 128;

    // --- A prep: A[a][t] = att[b][t][a] (transposed), bf16 hi/lo pairs ---
    const float* Ab = g_A + b * (TT * TT);
    #pragma unroll
    for (int it = 0; it < 16; ++it) {
        const int i  = it * 128 + tid;
        const int a  = i & 63, tp = i >> 6;        // tp = t/2, 0..31
        const float v0 = Ab[(2 * tp)     * TT + a];
        const float v1 = Ab[(2 * tp + 1) * TT + a];
        const float h0 = bf16_round(v0), h1 = bf16_round(v1);
        sAh[a * SA_STRIDE + tp] = pack_bf16x2(h0, h1);
        sAl[a * SA_STRIDE + tp] = pack_bf16x2(v0 - h0, v1 - h1);
    }

    // --- src tile: sS[t][c] fp32, 64x128 via float4 ---
    const float* sb = src + (size_t)b * TT * ND + colbase;
    #pragma unroll
    for (int it = 0; it < 16; ++it) {
        const int i = it * 128 + tid;
        const int t = i >> 5, c4 = i & 31;
        const float4 v = *reinterpret_cast<const float4*>(sb + (size_t)t * ND + c4 * 4);
        *reinterpret_cast<float4*>(sS + t * SS_STRIDE + c4 * 4) = v;
    }
    __syncthreads();

    const int g   = lane >> 2;     // 0..7
    const int tg  = lane & 3;      // 0..3
    const int n0w = warp * 32;

    float acc[4][4][4];
    #pragma unroll
    for (int mt = 0; mt < 4; ++mt)
        #pragma unroll
        for (int nt = 0; nt < 4; ++nt)
            #pragma unroll
            for (int f = 0; f < 4; ++f) acc[mt][nt][f] = 0.f;

    #pragma unroll
    for (int ks = 0; ks < 4; ++ks) {          // k = t, 16 per step
        uint32_t Ah[4][4], Al[4][4];
        #pragma unroll
        for (int mt = 0; mt < 4; ++mt) {
            const int r0 = (mt * 16 + g) * SA_STRIDE + ks * 8 + tg;
            const int r1 = r0 + 8 * SA_STRIDE;
            Ah[mt][0] = sAh[r0];     Ah[mt][1] = sAh[r1];
            Ah[mt][2] = sAh[r0 + 4]; Ah[mt][3] = sAh[r1 + 4];
            Al[mt][0] = sAl[r0];     Al[mt][1] = sAl[r1];
            Al[mt][2] = sAl[r0 + 4]; Al[mt][3] = sAl[r1 + 4];
        }
        #pragma unroll
        for (int nt = 0; nt < 4; ++nt) {
            const int c  = n0w + nt * 8 + g;
            const int t0 = ks * 16 + 2 * tg;
            const float v0 = sS[(t0)     * SS_STRIDE + c];
            const float v1 = sS[(t0 + 1) * SS_STRIDE + c];
            const float v2 = sS[(t0 + 8) * SS_STRIDE + c];
            const float v3 = sS[(t0 + 9) * SS_STRIDE + c];
            const float h0 = bf16_round(v0), h1 = bf16_round(v1);
            const float h2 = bf16_round(v2), h3 = bf16_round(v3);
            const uint32_t bh0 = pack_bf16x2(h0, h1);
            const uint32_t bh1 = pack_bf16x2(h2, h3);
            const uint32_t bl0 = pack_bf16x2(v0 - h0, v1 - h1);
            const uint32_t bl1 = pack_bf16x2(v2 - h2, v3 - h3);
            #pragma unroll
            for (int mt = 0; mt < 4; ++mt) {
                mma_bf16(acc[mt][nt], Ah[mt], bh0, bh1);
                mma_bf16(acc[mt][nt], Al[mt], bh0, bh1);
                mma_bf16(acc[mt][nt], Ah[mt], bl0, bl1);
            }
        }
    }

    // --- epilogue: out = mixed + src (fp32 residual from smem tile) ---
    float* ob = out + (size_t)b * TT * ND + colbase;
    #pragma unroll
    for (int mt = 0; mt < 4; ++mt) {
        const int a0 = mt * 16 + g;
        #pragma unroll
        for (int nt = 0; nt < 4; ++nt) {
            const int c = n0w + nt * 8 + 2 * tg;
            float2 v0, v1;
            v0.x = acc[mt][nt][0] + sS[a0 * SS_STRIDE + c];
            v0.y = acc[mt][nt][1] + sS[a0 * SS_STRIDE + c + 1];
            v1.x = acc[mt][nt][2] + sS[(a0 + 8) * SS_STRIDE + c];
            v1.y = acc[mt][nt][3] + sS[(a0 + 8) * SS_STRIDE + c + 1];
            *reinterpret_cast<float2*>(ob + (size_t)a0       * ND + c) = v0;
            *reinterpret_cast<float2*>(ob + (size_t)(a0 + 8) * ND + c) = v1;
        }
    }
}

// ---------------------------------------------------------------------------
extern "C" void kernel_launch(void* const* d_in, const int* in_sizes, int n_in,
                              void* d_out, int out_size) {
    const float *src = nullptr, *wt1 = nullptr, *wt2 = nullptr, *wt3 = nullptr;
    for (int i = 0; i < n_in; ++i) {
        const int s = in_sizes[i];
        if      (s == BB * TT * NN * DD) src = (const float*)d_in[i];
        else if (s == DD)                wt1 = (const float*)d_in[i];
        else if (s == NN * DD)           wt2 = (const float*)d_in[i];
        else if (s == NN)                wt3 = (const float*)d_in[i];
    }
    float* out = (float*)d_out;

    static bool attr_done = false;
    if (!attr_done) {
        cudaFuncSetAttribute(mix_kernel,
                             cudaFuncAttributeMaxDynamicSharedMemorySize,
                             MIX_SMEM_BYTES);
        attr_done = true;
    }

    qk_kernel<<<BT, 256>>>(src, wt1, wt3);
    m_kernel<<<dim3(BB, 8), 256>>>(wt2);
    scores_kernel<<<dim3(BB, 4), 256>>>();
    softmax_kernel<<<512, 256>>>();
    mix_kernel<<<dim3(ND / 128, BB), 128, MIX_SMEM_BYTES>>>(src, out);
}